// round 8
// baseline (speedup 1.0000x reference)
#include <cuda_runtime.h>
#include <cstdint>

#define BATCH 32
#define HH 512
#define WW 512
#define WPR 16              // u32 words per row (512 bits)

typedef unsigned long long u64;

// ---------------- global scratch (no allocation allowed) ----------------
__device__ __align__(16) unsigned g_maskP[BATCH * HH * WPR];
__device__ __align__(16) unsigned g_maskG[BATCH * HH * WPR];
__device__ double g_sums[BATCH][3];   // 0: sum p, 1: sum g, 2: sum p*g
__device__ int    g_cnt[BATCH][9];    // pe,ge,pei, pm,gm,pmi, pj,gj,pji
__device__ int    g_dist[2][BATCH];   // sum of clamped chebyshev distances (atomic acc)
__device__ int    g_non[2][BATCH];    // count of target-on pixels (atomic acc)

// ---------------- phase A: register-resident stencil, no data smem ----------------
// Warp unit: (batch b, column stripe sx in 0..3 of 128 cols, row band ry in 0..15 of 32 rows).
// Lane owns 4 consecutive columns (one float4 per row per image).
__global__ void __launch_bounds__(256) phaseA(const float* __restrict__ pred,
                                              const float* __restrict__ gt) {
    __shared__ float rf[8][3];
    __shared__ int   ri[8][5];

    int warp = threadIdx.x >> 5;
    int lane = threadIdx.x & 31;
    int w    = blockIdx.x * 8 + warp;      // 0..2047
    int b    = w >> 6;                     // all 8 warps of a block share b
    int rem  = w & 63;
    int sx   = rem & 3;
    int r0   = (rem >> 2) * 32;
    int col  = sx * 128 + lane * 4;
    int v4   = sx * 32 + lane;             // float4 index within a row

    const float* pb = pred + (size_t)b * HH * WW;
    const float* gb = gt   + (size_t)b * HH * WW;

    float hp0[4], hp1[4], hp2[4], hg0[4], hg1[4], hg2[4];
    float pC[4], gC[4], pN[4], gN[4];

    auto loadRow = [&](int r, float p[4], float g[4], float hp[4], float hg[4]) {
        if (r < 0 || r >= HH) {
            #pragma unroll
            for (int j = 0; j < 4; j++) { p[j]=0.f; g[j]=0.f; hp[j]=0.f; hg[j]=0.f; }
            return;
        }
        float4 pv = ((const float4*)(pb + (size_t)r * WW))[v4];
        float4 gv = ((const float4*)(gb + (size_t)r * WW))[v4];
        p[0]=pv.x; p[1]=pv.y; p[2]=pv.z; p[3]=pv.w;
        g[0]=gv.x; g[1]=gv.y; g[2]=gv.z; g[3]=gv.w;
        float lp = __shfl_up_sync(0xffffffffu, p[3], 1);
        float lg = __shfl_up_sync(0xffffffffu, g[3], 1);
        float rp = __shfl_down_sync(0xffffffffu, p[0], 1);
        float rg = __shfl_down_sync(0xffffffffu, g[0], 1);
        if (lane == 0) {
            lp = (sx > 0) ? pb[(size_t)r * WW + col - 1] : 0.f;
            lg = (sx > 0) ? gb[(size_t)r * WW + col - 1] : 0.f;
        }
        if (lane == 31) {
            rp = (sx < 3) ? pb[(size_t)r * WW + col + 4] : 0.f;
            rg = (sx < 3) ? gb[(size_t)r * WW + col + 4] : 0.f;
        }
        hp[0]=lp+p[0]+p[1]; hp[1]=p[0]+p[1]+p[2]; hp[2]=p[1]+p[2]+p[3]; hp[3]=p[2]+p[3]+rp;
        hg[0]=lg+g[0]+g[1]; hg[1]=g[0]+g[1]+g[2]; hg[2]=g[1]+g[2]+g[3]; hg[3]=g[2]+g[3]+rg;
    };

    { float d0[4], d1[4]; loadRow(r0 - 1, d0, d1, hp0, hg0); }
    loadRow(r0, pC, gC, hp1, hg1);

    float accP = 0.f, accG = 0.f, accPG = 0.f;
    int c0=0,c1=0,c2=0,c3=0,c4=0,c5=0,c6=0,c7=0,c8=0;

    #pragma unroll 4
    for (int y = 0; y < 32; y++) {
        loadRow(r0 + y + 1, pN, gN, hp2, hg2);
        unsigned nibP = 0, nibG = 0;
        #pragma unroll
        for (int j = 0; j < 4; j++) {
            float p = pC[j], g = gC[j];
            float np = hp0[j] + hp1[j] + hp2[j] - p;   // 8-neighbor sum (pred)
            float ng = hg0[j] + hg1[j] + hg2[j] - g;   // 8-neighbor sum (gt, exact int)
            bool pon = p > 0.5f, gon = g > 0.5f;
            accP += p; accG += g; accPG += p * g;
            bool pe = pon && (np == 1.f), pm = pon && (np == 2.f), pj = pon && (np > 2.f);
            bool ge = gon && (ng == 1.f), gm = gon && (ng == 2.f), gj = gon && (ng > 2.f);
            c0 += pe; c1 += ge; c2 += (pe && ge);
            c3 += pm; c4 += gm; c5 += (pm && gm);
            c6 += pj; c7 += gj; c8 += (pj && gj);
            nibP |= ((unsigned)pon) << j;
            nibG |= ((unsigned)gon) << j;
        }
        // nibble butterfly: group of 8 lanes assembles one u32 word (32 cols)
        unsigned v = nibP, o;
        o = __shfl_xor_sync(0xffffffffu, v, 1); v = (lane & 1) ? ((v << 4)  | o) : (v | (o << 4));
        o = __shfl_xor_sync(0xffffffffu, v, 2); v = (lane & 2) ? ((v << 8)  | o) : (v | (o << 8));
        o = __shfl_xor_sync(0xffffffffu, v, 4); v = (lane & 4) ? ((v << 16) | o) : (v | (o << 16));
        unsigned vg = nibG;
        o = __shfl_xor_sync(0xffffffffu, vg, 1); vg = (lane & 1) ? ((vg << 4)  | o) : (vg | (o << 4));
        o = __shfl_xor_sync(0xffffffffu, vg, 2); vg = (lane & 2) ? ((vg << 8)  | o) : (vg | (o << 8));
        o = __shfl_xor_sync(0xffffffffu, vg, 4); vg = (lane & 4) ? ((vg << 16) | o) : (vg | (o << 16));
        if ((lane & 7) == 0) {
            size_t base = ((size_t)b * HH + r0 + y) * WPR + sx * 4 + (lane >> 3);
            g_maskP[base] = v;
            g_maskG[base] = vg;
        }
        #pragma unroll
        for (int j = 0; j < 4; j++) {
            hp0[j]=hp1[j]; hp1[j]=hp2[j]; hg0[j]=hg1[j]; hg1[j]=hg2[j];
            pC[j]=pN[j];   gC[j]=gN[j];
        }
    }

    // warp reduce: 3 floats + 9 counters packed into u16 pairs (per-lane max 128)
    int u0 = c0 | (c1 << 16);
    int u1 = c2 | (c3 << 16);
    int u2 = c4 | (c5 << 16);
    int u3 = c6 | (c7 << 16);
    int u4 = c8;
    #pragma unroll
    for (int of = 16; of > 0; of >>= 1) {
        accP  += __shfl_down_sync(0xffffffffu, accP,  of);
        accG  += __shfl_down_sync(0xffffffffu, accG,  of);
        accPG += __shfl_down_sync(0xffffffffu, accPG, of);
        u0 += __shfl_down_sync(0xffffffffu, u0, of);
        u1 += __shfl_down_sync(0xffffffffu, u1, of);
        u2 += __shfl_down_sync(0xffffffffu, u2, of);
        u3 += __shfl_down_sync(0xffffffffu, u3, of);
        u4 += __shfl_down_sync(0xffffffffu, u4, of);
    }
    if (lane == 0) {
        rf[warp][0] = accP; rf[warp][1] = accG; rf[warp][2] = accPG;
        ri[warp][0] = u0; ri[warp][1] = u1; ri[warp][2] = u2; ri[warp][3] = u3; ri[warp][4] = u4;
    }
    __syncthreads();
    if (warp == 0 && lane < 8) {
        float b0 = rf[lane][0], b1 = rf[lane][1], b2 = rf[lane][2];
        int v0 = ri[lane][0], v1 = ri[lane][1], v2 = ri[lane][2], v3 = ri[lane][3], v4x = ri[lane][4];
        #pragma unroll
        for (int of = 4; of > 0; of >>= 1) {
            b0 += __shfl_down_sync(0x000000ffu, b0, of);
            b1 += __shfl_down_sync(0x000000ffu, b1, of);
            b2 += __shfl_down_sync(0x000000ffu, b2, of);
            v0 += __shfl_down_sync(0x000000ffu, v0, of);
            v1 += __shfl_down_sync(0x000000ffu, v1, of);
            v2 += __shfl_down_sync(0x000000ffu, v2, of);
            v3 += __shfl_down_sync(0x000000ffu, v3, of);
            v4x += __shfl_down_sync(0x000000ffu, v4x, of);
        }
        if (lane == 0) {
            atomicAdd(&g_sums[b][0], (double)b0);
            atomicAdd(&g_sums[b][1], (double)b1);
            atomicAdd(&g_sums[b][2], (double)b2);
            atomicAdd(&g_cnt[b][0], v0 & 0xffff);
            atomicAdd(&g_cnt[b][1], v0 >> 16);
            atomicAdd(&g_cnt[b][2], v1 & 0xffff);
            atomicAdd(&g_cnt[b][3], v1 >> 16);
            atomicAdd(&g_cnt[b][4], v2 & 0xffff);
            atomicAdd(&g_cnt[b][5], v2 >> 16);
            atomicAdd(&g_cnt[b][6], v3 & 0xffff);
            atomicAdd(&g_cnt[b][7], v3 >> 16);
            atomicAdd(&g_cnt[b][8], v4x);
        }
    }
}

// ---------------- phase B: bit-packed chebyshev distance sums, 2 row-chunks ----------------
// Each CTA handles (dir, b, chunk): 256 target rows, ref loaded with 9-row halo.
// After d dilation rounds, local rows [d, 274-d) are exact; counting rows [9,265)
// are always within that region for d<=9.
#define CROWS 256
#define HALO  9
#define LROWS (CROWS + 2 * HALO)    // 274
#define LW    (LROWS * 8)           // 2192 u64

__global__ void __launch_bounds__(512) phaseB() {
    extern __shared__ u64 sh[];
    u64* T  = sh;               // 2048 (core target rows)
    u64* A  = sh + 2048;        // 2192
    u64* Bu = A + LW;           // 2192

    int cid = blockIdx.x;       // 0..127
    int ch  = cid & 1;
    int b   = (cid >> 1) & 31;
    int dir = cid >> 6;         // 0: p2g (tgt=pred), 1: g2p (tgt=gt)

    const u64* tgt = (const u64*)(dir == 0 ? g_maskP : g_maskG) + (size_t)b * HH * 8;
    const u64* ref = (const u64*)(dir == 0 ? g_maskG : g_maskP) + (size_t)b * HH * 8;

    int t = threadIdx.x;
    int rbase = ch * CROWS - HALO;

    int non = 0;
    for (int k = t; k < CROWS * 8; k += 512) {
        u64 tv = tgt[(size_t)(ch * CROWS) * 8 + k];
        T[k] = tv;
        non += __popcll(tv);
    }
    for (int k = t; k < LW; k += 512) {
        int gr = rbase + (k >> 3);
        A[k] = (gr >= 0 && gr < HH) ? ref[(size_t)gr * 8 + (k & 7)] : 0ull;
    }
    __syncthreads();

    int cntNot = 0;
    for (int d = 1; d <= 9; d++) {
        // horizontal dilation
        for (int k = t; k < LW; k += 512) {
            int j = k & 7;
            u64 v = A[k];
            u64 h = v | (v << 1) | (v >> 1);
            if (j > 0) h |= A[k - 1] >> 63;
            if (j < 7) h |= A[k + 1] << 63;
            Bu[k] = h;
        }
        __syncthreads();
        // vertical dilation + count uncovered core target bits
        int roundCnt = 0;
        for (int k = t; k < LW; k += 512) {
            int lr = k >> 3;
            u64 v = Bu[k];
            if (lr > 0)         v |= Bu[k - 8];
            if (lr < LROWS - 1) v |= Bu[k + 8];
            A[k] = v;
            if (lr >= HALO && lr < HALO + CROWS)
                roundCnt += __popcll(T[(lr - HALO) * 8 + (k & 7)] & ~v);
        }
        cntNot += roundCnt;
        if (__syncthreads_count(roundCnt) == 0) break;   // also the barrier
    }

    #pragma unroll
    for (int o = 16; o > 0; o >>= 1) {
        non    += __shfl_down_sync(0xffffffffu, non, o);
        cntNot += __shfl_down_sync(0xffffffffu, cntNot, o);
    }
    int* ired = (int*)sh;   // smem fully consumed, last barrier passed
    int wid = t >> 5, lane = t & 31;
    if (lane == 0) { ired[wid * 2] = non; ired[wid * 2 + 1] = cntNot; }
    __syncthreads();
    if (t == 0) {
        int N = 0, C = 0;
        for (int wv = 0; wv < 16; wv++) { N += ired[wv * 2]; C += ired[wv * 2 + 1]; }
        atomicAdd(&g_non[dir][b], N);
        atomicAdd(&g_dist[dir][b], N + C);
    }
}

// ---------------- phase C: final combine (fp32) + re-zero accumulators ----------------
__global__ void phaseC(float* out) {
    int b = threadIdx.x;   // 32 threads
    float dice_t = 0.f, s_t = 0.f, m_t = 0.f;
    if (b < BATCH) {
        float psum  = (float)g_sums[b][0];
        float gsum  = (float)g_sums[b][1];
        float inter = (float)g_sums[b][2];
        dice_t = __fdividef(2.f * inter + 1.f, psum + gsum + 1.f);

        float pe = (float)g_cnt[b][0], ge = (float)g_cnt[b][1], pei = (float)g_cnt[b][2];
        float pm = (float)g_cnt[b][3], gm = (float)g_cnt[b][4], pmi = (float)g_cnt[b][5];
        float pj = (float)g_cnt[b][6], gj = (float)g_cnt[b][7], pji = (float)g_cnt[b][8];
        float e_iou = __fdividef(pei + 1.f, pe + ge - pei + 1.f);
        float m_iou = __fdividef(pmi + 1.f, pm + gm - pmi + 1.f);
        float j_iou = __fdividef(pji + 1.f, pj + gj - pji + 1.f);
        float total = ge + gj + gm + 1.f;
        s_t = 1.f - __fdividef(ge * e_iou + gj * j_iou + gm * m_iou, total);

        float p2g = __fdividef((float)g_dist[0][b], (float)g_non[0][b] + 1.f);
        float g2p = __fdividef((float)g_dist[1][b], (float)g_non[1][b] + 1.f);
        m_t = ((p2g + g2p) * 0.5f) * 0.1f;

        // re-zero accumulators for the next graph replay (each thread owns slot b)
        g_sums[b][0] = 0.0; g_sums[b][1] = 0.0; g_sums[b][2] = 0.0;
        #pragma unroll
        for (int i = 0; i < 9; i++) g_cnt[b][i] = 0;
        g_dist[0][b] = 0; g_dist[1][b] = 0;
        g_non[0][b]  = 0; g_non[1][b]  = 0;
    }
    #pragma unroll
    for (int o = 16; o > 0; o >>= 1) {
        dice_t += __shfl_down_sync(0xffffffffu, dice_t, o);
        s_t    += __shfl_down_sync(0xffffffffu, s_t, o);
        m_t    += __shfl_down_sync(0xffffffffu, m_t, o);
    }
    if (b == 0) {
        float dice_loss = 1.f - dice_t * (1.f / BATCH);
        float s = s_t * (1.f / BATCH);
        float m = m_t * (1.f / BATCH);
        float avg = (dice_loss + s + m) * (1.f / 3.f);
        float r = __fdividef(dice_loss, dice_loss + 1.f) * avg
                + __fdividef(s, s + 1.f) * avg
                + __fdividef(m, m + 1.f) * avg;
        out[0] = r;
    }
}

// ---------------- launch ----------------
extern "C" void kernel_launch(void* const* d_in, const int* in_sizes, int n_in,
                              void* d_out, int out_size) {
    const float* pred = (const float*)d_in[0];
    const float* gt   = (const float*)d_in[1];
    (void)in_sizes; (void)n_in; (void)out_size;

    const int BSMEM = (2048 + 2 * LW) * (int)sizeof(u64);   // 51456 bytes
    cudaFuncSetAttribute(phaseB, cudaFuncAttributeMaxDynamicSharedMemorySize, BSMEM);

    phaseA<<<256, 256>>>(pred, gt);
    phaseB<<<128, 512, BSMEM>>>();
    phaseC<<<1, 32>>>((float*)d_out);
}